// round 8
// baseline (speedup 1.0000x reference)
#include <cuda_runtime.h>

#define NPTS 50176
#define BATCH 64
#define KC 16
#define CAP 192

// -------- scratch (static device memory; no allocations) --------
__device__ unsigned g_bits1[BATCH][NPTS];
__device__ unsigned g_bits2[BATCH][NPTS];
__device__ float g_cent[BATCH][KC][3];
__device__ float g_sums[BATCH][KC][4];   // xyz sums + count

// -------- threefry2x32 (exact JAX algorithm) --------
__device__ __forceinline__ unsigned rotl32(unsigned v, int r) {
    return (v << r) | (v >> (32 - r));
}

__device__ __forceinline__ void tf2x32(unsigned k0, unsigned k1,
                                       unsigned x0, unsigned x1,
                                       unsigned& o0, unsigned& o1) {
    unsigned k2 = k0 ^ k1 ^ 0x1BD11BDAu;
    x0 += k0; x1 += k1;
#define TFR(r) { x0 += x1; x1 = rotl32(x1, r); x1 ^= x0; }
    TFR(13) TFR(15) TFR(26) TFR(6)
    x0 += k1; x1 += k2 + 1u;
    TFR(17) TFR(29) TFR(16) TFR(24)
    x0 += k2; x1 += k0 + 2u;
    TFR(13) TFR(15) TFR(26) TFR(6)
    x0 += k0; x1 += k1 + 3u;
    TFR(17) TFR(29) TFR(16) TFR(24)
    x0 += k1; x1 += k2 + 4u;
    TFR(13) TFR(15) TFR(26) TFR(6)
    x0 += k2; x1 += k0 + 5u;
#undef TFR
    o0 = x0; o1 = x1;
}

// -------- bit generation (jax_threefry_partitionable=True semantics) --------
// split(key, n)[i]         = tf(key, 0, i)              (foldlike: both words = child)
// random_bits(key,32,N)[j] = tf(key, 0, j).o0 ^ .o1     (partitionable 32-bit: XOR of halves)
//
// _shuffle carry chain per batch b:
//   root  = (0, 42)
//   key_b = tf(root, 0, b)                      // split(root, 64)[b]
//   key1  = tf(key_b, 0, 0); sub1 = tf(key_b, 0, 1)
//   sub2  = tf(key1, 0, 1)
//   bits1[j] = xor-words(tf(sub1, 0, j)) ; bits2[j] = xor-words(tf(sub2, 0, j))
__global__ void gen_bits_kernel() {
    int b = blockIdx.y;
    __shared__ unsigned sk[4];
    if (threadIdx.x == 0) {
        unsigned kb0, kb1, k10, k11, s10, s11, s20, s21;
        tf2x32(0u, 42u, 0u, (unsigned)b, kb0, kb1);   // key_b
        tf2x32(kb0, kb1, 0u, 0u, k10, k11);           // key1 (carry)
        tf2x32(kb0, kb1, 0u, 1u, s10, s11);           // sub1
        tf2x32(k10, k11, 0u, 1u, s20, s21);           // sub2
        sk[0] = s10; sk[1] = s11; sk[2] = s20; sk[3] = s21;
    }
    __syncthreads();
    int j = blockIdx.x * blockDim.x + threadIdx.x;
    if (j < NPTS) {
        unsigned o0, o1;
        tf2x32(sk[0], sk[1], 0u, (unsigned)j, o0, o1);
        g_bits1[b][j] = o0 ^ o1;                       // XOR of counter-half outputs
        tf2x32(sk[2], sk[3], 0u, (unsigned)j, o0, o1);
        g_bits2[b][j] = o0 ^ o1;
    }
}

// -------- stable order-statistic selection --------
struct SelSh {
    unsigned hist[4096];                 // counts -> exclusive scan (in place)
    unsigned wsum[32];
    unsigned long long lists[KC][CAP];
    unsigned listCnt[KC];
    int tb[KC];
    unsigned wr[KC];
    int ranks[KC];
    int outIdx[KC];
};

// For ranks[j] in [0,N): outIdx[j] = index i such that stable rank of
// (keys[i], i) equals ranks[j].
__device__ void select_ranks(const unsigned* __restrict__ keys, SelSh& sh) {
    int t = threadIdx.x;          // 1024 threads
    int lane = t & 31, wid = t >> 5;

    for (int i = t; i < 4096; i += 1024) sh.hist[i] = 0u;
    if (t < KC) sh.listCnt[t] = 0u;
    __syncthreads();

    for (int i = t; i < NPTS; i += 1024)
        atomicAdd(&sh.hist[keys[i] >> 20], 1u);
    __syncthreads();

    // exclusive scan of 4096 bins: 4 bins per thread + hierarchical shfl scan
    unsigned v0 = sh.hist[4*t], v1 = sh.hist[4*t+1], v2 = sh.hist[4*t+2], v3 = sh.hist[4*t+3];
    unsigned tot = v0 + v1 + v2 + v3;
    unsigned inc = tot;
    #pragma unroll
    for (int d = 1; d < 32; d <<= 1) {
        unsigned n = __shfl_up_sync(0xffffffffu, inc, d);
        if (lane >= d) inc += n;
    }
    if (lane == 31) sh.wsum[wid] = inc;
    __syncthreads();
    if (wid == 0) {
        unsigned w = sh.wsum[lane];
        unsigned winc = w;
        #pragma unroll
        for (int d = 1; d < 32; d <<= 1) {
            unsigned n = __shfl_up_sync(0xffffffffu, winc, d);
            if (lane >= d) winc += n;
        }
        sh.wsum[lane] = winc - w;   // exclusive warp offsets
    }
    __syncthreads();
    unsigned base = sh.wsum[wid] + (inc - tot);
    sh.hist[4*t]   = base;
    sh.hist[4*t+1] = base + v0;
    sh.hist[4*t+2] = base + v0 + v1;
    sh.hist[4*t+3] = base + v0 + v1 + v2;
    __syncthreads();

    if (t < KC) {
        unsigned r = (unsigned)sh.ranks[t];
        int lo = 0, hi = 4095;
        while (lo < hi) {                 // last bin with scan[bin] <= r
            int mid = (lo + hi + 1) >> 1;
            if (sh.hist[mid] <= r) lo = mid; else hi = mid - 1;
        }
        sh.tb[t] = lo;
        sh.wr[t] = r - sh.hist[lo];
    }
    __syncthreads();

    for (int i = t; i < NPTS; i += 1024) {
        unsigned key = keys[i];
        int bin = (int)(key >> 20);
        #pragma unroll
        for (int j = 0; j < KC; j++) {
            if (bin == sh.tb[j]) {
                unsigned p = atomicAdd(&sh.listCnt[j], 1u);
                if (p < CAP)
                    sh.lists[j][p] = ((unsigned long long)key << 32) | (unsigned)i;
            }
        }
    }
    __syncthreads();

    if (t < KC) {
        int n = min((int)sh.listCnt[t], CAP);
        // stable via 64-bit (key, idx) compare
        for (int a = 1; a < n; a++) {
            unsigned long long v = sh.lists[t][a];
            int q = a - 1;
            while (q >= 0 && sh.lists[t][q] > v) { sh.lists[t][q+1] = sh.lists[t][q]; q--; }
            sh.lists[t][q+1] = v;
        }
        sh.outIdx[t] = (int)(sh.lists[t][sh.wr[t]] & 0xFFFFFFFFull);
    }
    __syncthreads();
}

__global__ __launch_bounds__(1024) void select_kernel(const float* __restrict__ x) {
    __shared__ SelSh sh;
    int b = blockIdx.x;
    int t = threadIdx.x;

    // Stage A: positions of the 16 smallest round-2 keys (stable)
    if (t < KC) sh.ranks[t] = t;
    __syncthreads();
    select_ranks(g_bits2[b], sh);

    // Stage B: round-1 elements at those stable ranks
    if (t < KC) sh.ranks[t] = sh.outIdx[t];
    __syncthreads();
    select_ranks(g_bits1[b], sh);

    if (t < 48) {
        int k = t / 3, c = t % 3;
        int idx = sh.outIdx[k];
        g_cent[b][k][c] = x[(size_t)b * NPTS * 3 + (size_t)idx * 3 + c];
    }
    if (t < 64) ((float*)g_sums[b])[t] = 0.f;
}

// -------- Lloyd iteration --------
#define PPB 3136   // NPTS / 16 blocks per batch

__global__ __launch_bounds__(256, 1) void accum_kernel(const float* __restrict__ x) {
    int b = blockIdx.y;
    const float* xb = x + (size_t)b * NPTS * 3;

    float c0[KC], c1[KC], c2[KC];
    #pragma unroll
    for (int k = 0; k < KC; k++) {
        c0[k] = g_cent[b][k][0];
        c1[k] = g_cent[b][k][1];
        c2[k] = g_cent[b][k][2];
    }
    float a0[KC], a1[KC], a2[KC], a3[KC];
    #pragma unroll
    for (int k = 0; k < KC; k++) { a0[k]=0.f; a1[k]=0.f; a2[k]=0.f; a3[k]=0.f; }

    int base = blockIdx.x * PPB;
    for (int i = base + threadIdx.x; i < base + PPB; i += 256) {
        float x0 = xb[3*i], x1 = xb[3*i+1], x2 = xb[3*i+2];
        float d0 = x0 - c0[0], d1 = x1 - c1[0], d2 = x2 - c2[0];
        float best = fmaf(d0, d0, fmaf(d1, d1, d2 * d2));
        int bk = 0;
        #pragma unroll
        for (int k = 1; k < KC; k++) {
            d0 = x0 - c0[k]; d1 = x1 - c1[k]; d2 = x2 - c2[k];
            float d = fmaf(d0, d0, fmaf(d1, d1, d2 * d2));
            if (d < best) { best = d; bk = k; }   // strict < : first-min like argmin
        }
        #pragma unroll
        for (int k = 0; k < KC; k++) {
            if (bk == k) { a0[k] += x0; a1[k] += x1; a2[k] += x2; a3[k] += 1.f; }
        }
    }

    // warp shuffle reduction of all 64 accumulator slots
    #pragma unroll
    for (int k = 0; k < KC; k++) {
        #pragma unroll
        for (int off = 16; off > 0; off >>= 1) {
            a0[k] += __shfl_down_sync(0xffffffffu, a0[k], off);
            a1[k] += __shfl_down_sync(0xffffffffu, a1[k], off);
            a2[k] += __shfl_down_sync(0xffffffffu, a2[k], off);
            a3[k] += __shfl_down_sync(0xffffffffu, a3[k], off);
        }
    }

    __shared__ float ssum[KC][4];
    if (threadIdx.x < 64) ((float*)ssum)[threadIdx.x] = 0.f;
    __syncthreads();
    if ((threadIdx.x & 31) == 0) {
        #pragma unroll
        for (int k = 0; k < KC; k++) {
            atomicAdd(&ssum[k][0], a0[k]);
            atomicAdd(&ssum[k][1], a1[k]);
            atomicAdd(&ssum[k][2], a2[k]);
            atomicAdd(&ssum[k][3], a3[k]);
        }
    }
    __syncthreads();
    if (threadIdx.x < 64) {
        float v = ((float*)ssum)[threadIdx.x];
        atomicAdd(&((float*)g_sums[b])[threadIdx.x], v);
    }
}

__global__ void update_kernel(float* __restrict__ out) {
    int b = blockIdx.x, t = threadIdx.x;   // 64 threads
    float nc = 0.f;
    if (t < 48) {
        int k = t / 3, c = t % 3;
        float s = g_sums[b][k][c];
        float cnt = g_sums[b][k][3];
        nc = s / cnt;
    }
    __syncthreads();
    if (t < 64) ((float*)g_sums[b])[t] = 0.f;   // reset for next iteration
    if (t < 48) {
        int k = t / 3, c = t % 3;
        g_cent[b][k][c] = nc;
        out[b * 48 + t] = nc;
    }
}

// -------- launch --------
extern "C" void kernel_launch(void* const* d_in, const int* in_sizes, int n_in,
                              void* d_out, int out_size) {
    const float* x = (const float*)d_in[0];
    float* out = (float*)d_out;

    gen_bits_kernel<<<dim3(196, BATCH), 256>>>();   // 196*256 = 50176 = NPTS
    select_kernel<<<BATCH, 1024>>>(x);
    for (int it = 0; it < 10; it++) {
        accum_kernel<<<dim3(16, BATCH), 256>>>(x);
        update_kernel<<<BATCH, 64>>>(out);
    }
}

// round 9
// speedup vs baseline: 1.2098x; 1.2098x over previous
#include <cuda_runtime.h>

#define NPTS 50176
#define BATCH 64
#define KC 16
#define CAP 192

// -------- scratch (static device memory; no allocations) --------
__device__ unsigned g_bits1[BATCH][NPTS];
__device__ unsigned g_bits2[BATCH][NPTS];
__device__ float g_cent[BATCH][KC][3];
__device__ float g_sums3[3][BATCH][KC][4];   // triple-buffered xyz sums + count

// -------- packed f32x2 helpers --------
__device__ __forceinline__ unsigned long long pk2(float lo, float hi) {
    unsigned long long r;
    asm("mov.b64 %0, {%1, %2};" : "=l"(r) : "f"(lo), "f"(hi));
    return r;
}
__device__ __forceinline__ void upk2(unsigned long long v, float& lo, float& hi) {
    asm("mov.b64 {%0, %1}, %2;" : "=f"(lo), "=f"(hi) : "l"(v));
}
__device__ __forceinline__ unsigned long long add2(unsigned long long a, unsigned long long b) {
    unsigned long long r;
    asm("add.rn.f32x2 %0, %1, %2;" : "=l"(r) : "l"(a), "l"(b));
    return r;
}
__device__ __forceinline__ unsigned long long mul2(unsigned long long a, unsigned long long b) {
    unsigned long long r;
    asm("mul.rn.f32x2 %0, %1, %2;" : "=l"(r) : "l"(a), "l"(b));
    return r;
}
__device__ __forceinline__ unsigned long long fma2(unsigned long long a, unsigned long long b,
                                                   unsigned long long c) {
    unsigned long long r;
    asm("fma.rn.f32x2 %0, %1, %2, %3;" : "=l"(r) : "l"(a), "l"(b), "l"(c));
    return r;
}

// -------- threefry2x32 (exact JAX algorithm) --------
__device__ __forceinline__ unsigned rotl32(unsigned v, int r) {
    return (v << r) | (v >> (32 - r));
}

__device__ __forceinline__ void tf2x32(unsigned k0, unsigned k1,
                                       unsigned x0, unsigned x1,
                                       unsigned& o0, unsigned& o1) {
    unsigned k2 = k0 ^ k1 ^ 0x1BD11BDAu;
    x0 += k0; x1 += k1;
#define TFR(r) { x0 += x1; x1 = rotl32(x1, r); x1 ^= x0; }
    TFR(13) TFR(15) TFR(26) TFR(6)
    x0 += k1; x1 += k2 + 1u;
    TFR(17) TFR(29) TFR(16) TFR(24)
    x0 += k2; x1 += k0 + 2u;
    TFR(13) TFR(15) TFR(26) TFR(6)
    x0 += k0; x1 += k1 + 3u;
    TFR(17) TFR(29) TFR(16) TFR(24)
    x0 += k1; x1 += k2 + 4u;
    TFR(13) TFR(15) TFR(26) TFR(6)
    x0 += k2; x1 += k0 + 5u;
#undef TFR
    o0 = x0; o1 = x1;
}

// -------- bit generation (jax_threefry_partitionable=True semantics) --------
__global__ void gen_bits_kernel() {
    int b = blockIdx.y;
    __shared__ unsigned sk[4];
    if (threadIdx.x == 0) {
        unsigned kb0, kb1, k10, k11, s10, s11, s20, s21;
        tf2x32(0u, 42u, 0u, (unsigned)b, kb0, kb1);   // key_b
        tf2x32(kb0, kb1, 0u, 0u, k10, k11);           // key1 (carry)
        tf2x32(kb0, kb1, 0u, 1u, s10, s11);           // sub1
        tf2x32(k10, k11, 0u, 1u, s20, s21);           // sub2
        sk[0] = s10; sk[1] = s11; sk[2] = s20; sk[3] = s21;
    }
    __syncthreads();
    int j = blockIdx.x * blockDim.x + threadIdx.x;
    if (j < NPTS) {
        unsigned o0, o1;
        tf2x32(sk[0], sk[1], 0u, (unsigned)j, o0, o1);
        g_bits1[b][j] = o0 ^ o1;                       // XOR of counter-half outputs
        tf2x32(sk[2], sk[3], 0u, (unsigned)j, o0, o1);
        g_bits2[b][j] = o0 ^ o1;
    }
}

// -------- stable order-statistic selection --------
struct SelSh {
    unsigned hist[4096];
    unsigned wsum[32];
    unsigned long long lists[KC][CAP];
    unsigned listCnt[KC];
    int tb[KC];
    unsigned wr[KC];
    int ranks[KC];
    int outIdx[KC];
};

__device__ void select_ranks(const unsigned* __restrict__ keys, SelSh& sh) {
    int t = threadIdx.x;          // 1024 threads
    int lane = t & 31, wid = t >> 5;

    for (int i = t; i < 4096; i += 1024) sh.hist[i] = 0u;
    if (t < KC) sh.listCnt[t] = 0u;
    __syncthreads();

    for (int i = t; i < NPTS; i += 1024)
        atomicAdd(&sh.hist[keys[i] >> 20], 1u);
    __syncthreads();

    unsigned v0 = sh.hist[4*t], v1 = sh.hist[4*t+1], v2 = sh.hist[4*t+2], v3 = sh.hist[4*t+3];
    unsigned tot = v0 + v1 + v2 + v3;
    unsigned inc = tot;
    #pragma unroll
    for (int d = 1; d < 32; d <<= 1) {
        unsigned n = __shfl_up_sync(0xffffffffu, inc, d);
        if (lane >= d) inc += n;
    }
    if (lane == 31) sh.wsum[wid] = inc;
    __syncthreads();
    if (wid == 0) {
        unsigned w = sh.wsum[lane];
        unsigned winc = w;
        #pragma unroll
        for (int d = 1; d < 32; d <<= 1) {
            unsigned n = __shfl_up_sync(0xffffffffu, winc, d);
            if (lane >= d) winc += n;
        }
        sh.wsum[lane] = winc - w;
    }
    __syncthreads();
    unsigned base = sh.wsum[wid] + (inc - tot);
    sh.hist[4*t]   = base;
    sh.hist[4*t+1] = base + v0;
    sh.hist[4*t+2] = base + v0 + v1;
    sh.hist[4*t+3] = base + v0 + v1 + v2;
    __syncthreads();

    if (t < KC) {
        unsigned r = (unsigned)sh.ranks[t];
        int lo = 0, hi = 4095;
        while (lo < hi) {
            int mid = (lo + hi + 1) >> 1;
            if (sh.hist[mid] <= r) lo = mid; else hi = mid - 1;
        }
        sh.tb[t] = lo;
        sh.wr[t] = r - sh.hist[lo];
    }
    __syncthreads();

    for (int i = t; i < NPTS; i += 1024) {
        unsigned key = keys[i];
        int bin = (int)(key >> 20);
        #pragma unroll
        for (int j = 0; j < KC; j++) {
            if (bin == sh.tb[j]) {
                unsigned p = atomicAdd(&sh.listCnt[j], 1u);
                if (p < CAP)
                    sh.lists[j][p] = ((unsigned long long)key << 32) | (unsigned)i;
            }
        }
    }
    __syncthreads();

    if (t < KC) {
        int n = min((int)sh.listCnt[t], CAP);
        for (int a = 1; a < n; a++) {
            unsigned long long v = sh.lists[t][a];
            int q = a - 1;
            while (q >= 0 && sh.lists[t][q] > v) { sh.lists[t][q+1] = sh.lists[t][q]; q--; }
            sh.lists[t][q+1] = v;
        }
        sh.outIdx[t] = (int)(sh.lists[t][sh.wr[t]] & 0xFFFFFFFFull);
    }
    __syncthreads();
}

__global__ __launch_bounds__(1024) void select_kernel(const float* __restrict__ x) {
    __shared__ SelSh sh;
    int b = blockIdx.x;
    int t = threadIdx.x;

    if (t < KC) sh.ranks[t] = t;
    __syncthreads();
    select_ranks(g_bits2[b], sh);

    if (t < KC) sh.ranks[t] = sh.outIdx[t];
    __syncthreads();
    select_ranks(g_bits1[b], sh);

    if (t < 48) {
        int k = t / 3, c = t % 3;
        int idx = sh.outIdx[k];
        g_cent[b][k][c] = x[(size_t)b * NPTS * 3 + (size_t)idx * 3 + c];
    }
    // zero accumulation buffers 0 and 1 (launch it=0 accumulates into 0, it=1 into 1)
    if (t < 64)  ((float*)g_sums3[0][b])[t] = 0.f;
    else if (t < 128) ((float*)g_sums3[1][b])[t - 64] = 0.f;
}

// -------- fused Lloyd iteration (assign + accumulate + implicit update) --------
#define GRP_PER_BLK 784    // groups of 4 points; 16 blocks * 784 * 4 = 50176

__global__ __launch_bounds__(256) void accum_kernel(const float* __restrict__ x, int it) {
    int b = blockIdx.y;
    int tid = threadIdx.x;

    // --- compute this iteration's centroids from previous sums (or initial) ---
    __shared__ float sc[KC][3];
    if (tid < 48) {
        int k = tid / 3, c = tid % 3;
        if (it == 0) {
            sc[k][c] = g_cent[b][k][c];
        } else {
            const float* pb = (const float*)g_sums3[(it + 2) % 3][b];
            sc[k][c] = pb[k * 4 + c] / pb[k * 4 + 3];
        }
    }
    // zero the buffer the NEXT launch will accumulate into (nobody touches it this launch)
    if (blockIdx.x == 0 && tid >= 64 && tid < 128)
        ((float*)g_sums3[(it + 1) % 3][b])[tid - 64] = 0.f;
    __syncthreads();

    // packed negated centroids: pair p covers clusters 2p, 2p+1
    unsigned long long ncx[KC/2], ncy[KC/2], ncz[KC/2];
    #pragma unroll
    for (int p = 0; p < KC/2; p++) {
        ncx[p] = pk2(-sc[2*p][0], -sc[2*p+1][0]);
        ncy[p] = pk2(-sc[2*p][1], -sc[2*p+1][1]);
        ncz[p] = pk2(-sc[2*p][2], -sc[2*p+1][2]);
    }

    // packed accumulators: acc01[k] = (sum_x0, sum_x1), acc23[k] = (sum_x2, count)
    unsigned long long acc01[KC], acc23[KC];
    #pragma unroll
    for (int k = 0; k < KC; k++) { acc01[k] = 0ull; acc23[k] = 0ull; }

    const float4* xb4 = (const float4*)(x + (size_t)b * NPTS * 3);
    int gend = blockIdx.x * GRP_PER_BLK + GRP_PER_BLK;

    for (int g = blockIdx.x * GRP_PER_BLK + tid; g < gend; g += 256) {
        float4 A = xb4[3*g], Bv = xb4[3*g + 1], Cv = xb4[3*g + 2];
        float px[4], py[4], pz[4];
        px[0] = A.x;  py[0] = A.y;  pz[0] = A.z;
        px[1] = A.w;  py[1] = Bv.x; pz[1] = Bv.y;
        px[2] = Bv.z; py[2] = Bv.w; pz[2] = Cv.x;
        px[3] = Cv.y; py[3] = Cv.z; pz[3] = Cv.w;

        #pragma unroll
        for (int q = 0; q < 4; q++) {
            float x0 = px[q], x1 = py[q], x2 = pz[q];
            unsigned long long x00 = pk2(x0, x0);
            unsigned long long x11 = pk2(x1, x1);
            unsigned long long x22 = pk2(x2, x2);

            float best = 3.402823466e+38f;
            int bk = 0;
            #pragma unroll
            for (int p = 0; p < KC/2; p++) {
                unsigned long long d0 = add2(x00, ncx[p]);
                unsigned long long d1 = add2(x11, ncy[p]);
                unsigned long long d2 = add2(x22, ncz[p]);
                unsigned long long t = mul2(d0, d0);
                t = fma2(d1, d1, t);
                t = fma2(d2, d2, t);
                float slo, shi;
                upk2(t, slo, shi);
                if (slo < best) { best = slo; bk = 2*p; }
                if (shi < best) { best = shi; bk = 2*p + 1; }
            }

            unsigned long long x01 = pk2(x0, x1);
            unsigned long long x21 = pk2(x2, 1.0f);
            #pragma unroll
            for (int k = 0; k < KC; k++) {
                asm volatile(
                    "{\n\t.reg .pred p;\n\t"
                    "setp.eq.s32 p, %2, %3;\n\t"
                    "@p add.rn.f32x2 %0, %0, %4;\n\t"
                    "@p add.rn.f32x2 %1, %1, %5;\n\t}"
                    : "+l"(acc01[k]), "+l"(acc23[k])
                    : "r"(bk), "r"(k), "l"(x01), "l"(x21));
            }
        }
    }

    // warp shuffle reduction of packed accumulators
    #pragma unroll
    for (int k = 0; k < KC; k++) {
        #pragma unroll
        for (int off = 16; off > 0; off >>= 1) {
            acc01[k] = add2(acc01[k], __shfl_down_sync(0xffffffffu, acc01[k], off));
            acc23[k] = add2(acc23[k], __shfl_down_sync(0xffffffffu, acc23[k], off));
        }
    }

    __shared__ float ssum[KC][4];
    if (tid < 64) ((float*)ssum)[tid] = 0.f;
    __syncthreads();
    if ((tid & 31) == 0) {
        #pragma unroll
        for (int k = 0; k < KC; k++) {
            float s0, s1, s2, s3;
            upk2(acc01[k], s0, s1);
            upk2(acc23[k], s2, s3);
            atomicAdd(&ssum[k][0], s0);
            atomicAdd(&ssum[k][1], s1);
            atomicAdd(&ssum[k][2], s2);
            atomicAdd(&ssum[k][3], s3);
        }
    }
    __syncthreads();
    if (tid < 64) {
        float v = ((float*)ssum)[tid];
        atomicAdd(&((float*)g_sums3[it % 3][b])[tid], v);
    }
}

__global__ void finalize_kernel(float* __restrict__ out) {
    int b = blockIdx.x, t = threadIdx.x;   // 64 threads; last sums in buffer 9%3 == 0
    if (t < 48) {
        int k = t / 3, c = t % 3;
        const float* pb = (const float*)g_sums3[0][b];
        out[b * 48 + t] = pb[k * 4 + c] / pb[k * 4 + 3];
    }
}

// -------- launch --------
extern "C" void kernel_launch(void* const* d_in, const int* in_sizes, int n_in,
                              void* d_out, int out_size) {
    const float* x = (const float*)d_in[0];
    float* out = (float*)d_out;

    gen_bits_kernel<<<dim3(196, BATCH), 256>>>();   // 196*256 = 50176 = NPTS
    select_kernel<<<BATCH, 1024>>>(x);
    for (int it = 0; it < 10; it++) {
        accum_kernel<<<dim3(16, BATCH), 256>>>(x, it);
    }
    finalize_kernel<<<BATCH, 64>>>(out);
}